// round 14
// baseline (speedup 1.0000x reference)
#include <cuda_runtime.h>
#include <cuda_bf16.h>

#define B_ROWS 16384
#define L_COLS 1024
#define ROWS_PER_BLK 16
#define NBLKS (B_ROWS / ROWS_PER_BLK)   // 1024

// Per-block partial sums of row losses (no device allocation allowed).
__device__ float g_partials[NBLKS];

__device__ __forceinline__ float ex2_approx(float x) {
    float r;
    asm("ex2.approx.f32 %0, %1;" : "=f"(r) : "f"(x));
    return r;
}
__device__ __forceinline__ float rcp_approx(float x) {
    float r;
    asm("rcp.approx.f32 %0, %1;" : "=f"(r) : "f"(x));
    return r;
}

// e = 2^(c*log2e) = e^c ; r = rcp(e) = e^-c. Both MUFU ops (MUFU is ~4x
// underutilized here, so the extra RCP is free in pipe terms) — this deletes
// the per-element sign-flip ALU work. Accumulation: 1 ISETP + 2 pred-FADD.
#define EXP_ACC(cval, yval)                               \
    do {                                                  \
        const float e = ex2_approx((cval) * 1.4426950408889634f); \
        const float r = rcp_approx(e);                    \
        if (yval) pos += r; else neg += e;                \
    } while (0)

// 1024 blocks x 512 threads (16 warps). Warp w handles row blockIdx.x*16 + w.
// Each lane: 8 iterations of (float4 c, int4 y) -> 1024 elems/row.
// The kernel is ISSUE-bound (not DRAM-bound): minimize instructions/element.
__global__ void __launch_bounds__(512, 4)
bpmll_row_kernel(const float* __restrict__ c, const int* __restrict__ y,
                 float* __restrict__ partials) {
    const int t = threadIdx.x;
    const int warp = t >> 5;
    const int lane = t & 31;
    const int row = blockIdx.x * ROWS_PER_BLK + warp;

    const float4* __restrict__ c4 =
        reinterpret_cast<const float4*>(c + (size_t)row * L_COLS);
    const int4* __restrict__ y4 =
        reinterpret_cast<const int4*>(y + (size_t)row * L_COLS);

    float pos = 0.0f, neg = 0.0f;
    int yc = 0;

    #pragma unroll
    for (int i = 0; i < 8; i++) {
        const float4 cv = c4[i * 32 + lane];
        const int4 yv = y4[i * 32 + lane];

        // Unconditional label count: y values are exactly 0/1.
        yc += (yv.x + yv.y) + (yv.z + yv.w);

        EXP_ACC(cv.x, yv.x);
        EXP_ACC(cv.y, yv.y);
        EXP_ACC(cv.z, yv.z);
        EXP_ACC(cv.w, yv.w);
    }

    // Warp tree reduction (deterministic).
    #pragma unroll
    for (int off = 16; off > 0; off >>= 1) {
        pos += __shfl_down_sync(0xFFFFFFFFu, pos, off);
        neg += __shfl_down_sync(0xFFFFFFFFu, neg, off);
        yc  += __shfl_down_sync(0xFFFFFFFFu, yc, off);
    }

    __shared__ float s_loss[ROWS_PER_BLK];
    if (lane == 0) {
        const float yn = (float)yc;
        const float ybn = (float)(L_COLS - yc);
        s_loss[warp] = (pos * neg) / (yn * ybn);
    }
    __syncthreads();

    if (t == 0) {
        float sum = 0.0f;
        #pragma unroll
        for (int w = 0; w < ROWS_PER_BLK; w++) sum += s_loss[w];
        partials[blockIdx.x] = sum;
    }
    cudaTriggerProgrammaticLaunchCompletion();
}

// Single-block reduction of 1024 partials -> mean over 16384 rows.
// Launched with PDL; waits on the primary grid before reading partials.
__global__ void __launch_bounds__(256)
bpmll_reduce_kernel(const float* __restrict__ partials, float* __restrict__ out) {
    cudaGridDependencySynchronize();

    const int t = threadIdx.x;
    const float4 v = reinterpret_cast<const float4*>(partials)[t];  // 256*4 = 1024
    float s = (v.x + v.y) + (v.z + v.w);

    #pragma unroll
    for (int off = 16; off > 0; off >>= 1)
        s += __shfl_down_sync(0xFFFFFFFFu, s, off);

    __shared__ float s_w[8];
    const int warp = t >> 5;
    const int lane = t & 31;
    if (lane == 0) s_w[warp] = s;
    __syncthreads();

    if (t == 0) {
        float tot = 0.0f;
        #pragma unroll
        for (int w = 0; w < 8; w++) tot += s_w[w];
        out[0] = tot * (1.0f / (float)B_ROWS);
    }
}

extern "C" void kernel_launch(void* const* d_in, const int* in_sizes, int n_in,
                              void* d_out, int out_size) {
    const float* c = (const float*)d_in[0];
    const int* y = (const int*)d_in[1];
    float* out = (float*)d_out;

    float* partials = nullptr;
    cudaGetSymbolAddress((void**)&partials, g_partials);

    bpmll_row_kernel<<<NBLKS, 512>>>(c, y, partials);

    cudaLaunchConfig_t cfg = {};
    cfg.gridDim = dim3(1, 1, 1);
    cfg.blockDim = dim3(256, 1, 1);
    cfg.dynamicSmemBytes = 0;
    cfg.stream = 0;
    cudaLaunchAttribute attrs[1];
    attrs[0].id = cudaLaunchAttributeProgrammaticStreamSerialization;
    attrs[0].val.programmaticStreamSerializationAllowed = 1;
    cfg.attrs = attrs;
    cfg.numAttrs = 1;
    cudaLaunchKernelEx(&cfg, bpmll_reduce_kernel,
                       (const float*)partials, out);
}

// round 17
// speedup vs baseline: 1.2030x; 1.2030x over previous
#include <cuda_runtime.h>
#include <cuda_bf16.h>

#define B_ROWS 16384
#define L_COLS 1024
#define ROWS_PER_BLK 16
#define NBLKS (B_ROWS / ROWS_PER_BLK)   // 1024
#define NSLOTS 32
#define FIX_SCALE 4294967296.0          // 2^32

// Fence-free cross-block accumulators, spread over 32 L2 addresses to avoid
// same-address atomic serialization (no device allocation allowed).
__device__ unsigned long long g_acc[NSLOTS];
__device__ unsigned int g_count = 0u;

// 1024 blocks x 512 threads (16 warps). Warp w handles row blockIdx.x*16 + w.
// Each lane: 8 iterations of (float4 c, int4 y) -> 1024 elems/row.
// Finish: per-block loss sum -> 2^32 fixed point -> integer atomicAdd into
// slot (blockIdx & 31). Integer adds are exactly commutative => bitwise
// deterministic. Ordering without any fence: the count atomic is data-chained
// on the acc atomic's return value. Last block gathers the 32 slots with one
// warp of parallel atomicExch (read+reset in one op), writes the mean.
__global__ void __launch_bounds__(512, 4)
bpmll_fused_kernel(const float* __restrict__ c, const int* __restrict__ y,
                   float* __restrict__ out) {
    const int t = threadIdx.x;
    const int warp = t >> 5;
    const int lane = t & 31;
    const int row = blockIdx.x * ROWS_PER_BLK + warp;

    const float4* __restrict__ c4 =
        reinterpret_cast<const float4*>(c + (size_t)row * L_COLS);
    const int4* __restrict__ y4 =
        reinterpret_cast<const int4*>(y + (size_t)row * L_COLS);

    float pos = 0.0f, neg = 0.0f;
    int yc = 0;

    #pragma unroll
    for (int i = 0; i < 8; i++) {
        const float4 cv = c4[i * 32 + lane];
        const int4 yv = y4[i * 32 + lane];

        {
            const float e = __expf(yv.x ? -cv.x : cv.x);
            if (yv.x) { pos += e; yc++; } else { neg += e; }
        }
        {
            const float e = __expf(yv.y ? -cv.y : cv.y);
            if (yv.y) { pos += e; yc++; } else { neg += e; }
        }
        {
            const float e = __expf(yv.z ? -cv.z : cv.z);
            if (yv.z) { pos += e; yc++; } else { neg += e; }
        }
        {
            const float e = __expf(yv.w ? -cv.w : cv.w);
            if (yv.w) { pos += e; yc++; } else { neg += e; }
        }
    }

    // Warp tree reduction (deterministic).
    #pragma unroll
    for (int off = 16; off > 0; off >>= 1) {
        pos += __shfl_down_sync(0xFFFFFFFFu, pos, off);
        neg += __shfl_down_sync(0xFFFFFFFFu, neg, off);
        yc  += __shfl_down_sync(0xFFFFFFFFu, yc, off);
    }

    __shared__ float s_loss[ROWS_PER_BLK];
    __shared__ bool s_last;
    if (lane == 0) {
        const float yn = (float)yc;
        const float ybn = (float)(L_COLS - yc);
        s_loss[warp] = (pos * neg) / (yn * ybn);
    }
    __syncthreads();

    if (t == 0) {
        // Fixed order -> deterministic block sum.
        float sum = 0.0f;
        #pragma unroll
        for (int w = 0; w < ROWS_PER_BLK; w++) sum += s_loss[w];

        // 2^32 fixed point (double for the scale multiply; one per block).
        const unsigned long long fixed =
            (unsigned long long)((double)sum * FIX_SCALE + 0.5);

        // Slot add; returns old value => RMW completed at L2.
        const unsigned long long old =
            atomicAdd(&g_acc[blockIdx.x & (NSLOTS - 1)], fixed);

        // Chain the counter on the returned value (orders acc-add before
        // count-add with NO fence => no CCTL.IVALL L1 flush).
        const unsigned int dep = (unsigned int)(old & 1ULL);
        const unsigned int prev = atomicAdd(&g_count, 1u + dep - dep);
        s_last = (prev == (unsigned int)(NBLKS - 1));
    }
    __syncthreads();

    // Last block: warp 0 gathers the 32 slots in parallel (spread-address
    // atomicExch = read + reset in one op), reduces, writes the mean.
    if (s_last && warp == 0) {
        unsigned long long v = atomicExch(&g_acc[lane], 0ULL);

        #pragma unroll
        for (int off = 16; off > 0; off >>= 1)
            v += __shfl_down_sync(0xFFFFFFFFu, v, off);

        if (lane == 0) {
            out[0] = (float)((double)v * (1.0 / FIX_SCALE)
                             * (1.0 / (double)B_ROWS));
            atomicExch(&g_count, 0u);  // reset for next graph replay
        }
    }
}

extern "C" void kernel_launch(void* const* d_in, const int* in_sizes, int n_in,
                              void* d_out, int out_size) {
    const float* c = (const float*)d_in[0];
    const int* y = (const int*)d_in[1];
    float* out = (float*)d_out;

    bpmll_fused_kernel<<<NBLKS, 512>>>(c, y, out);
}